// round 3
// baseline (speedup 1.0000x reference)
#include <cuda_runtime.h>
#include <cstdint>

#define Nn    10000
#define Pp    2000
#define CTn   10
#define Ee    320000
#define DAE0  100
#define DAE1  20
#define GAE0  32
#define GAE1  20
#define FCAT  40
#define FEATn 64

typedef unsigned long long ull;

// ---------------- packed f32x2 helpers ----------------
__device__ __forceinline__ void fma2(ull &d, ull a, ull b) {
    asm("fma.rn.f32x2 %0, %1, %2, %0;" : "+l"(d) : "l"(a), "l"(b));
}
__device__ __forceinline__ ull pack2(float a, float b) {
    ull r; asm("mov.b64 %0, {%1,%2};" : "=l"(r) : "f"(a), "f"(b)); return r;
}
__device__ __forceinline__ float2 unpack2(ull v) {
    float2 r; asm("mov.b64 {%0,%1}, %2;" : "=f"(r.x), "=f"(r.y) : "l"(v)); return r;
}
__device__ __forceinline__ float celu1(float x) { return x > 0.f ? x : expm1f(x); }

// ---------------- device scratch ----------------
__device__ float g_dinv[Nn];
__device__ ull   g_h1p[4][Nn * 50];     // x@W1 split-K partials, packed pairs
__device__ float g_feat[Nn * FCAT];
__device__ ull   g_fdup[Nn * FCAT];
__device__ float g_hf  [Nn * GAE0];
__device__ float g_aggf[Nn * GAE0];
__device__ float g_hm  [Nn * 2 * GAE1];
__device__ float g_aggm[Nn * 2 * GAE1];
__device__ float g_zg  [Nn * FEATn];
__device__ float g_acc [4];

// ---------------- K0: init / degree / dinv ----------------
__global__ void k_init() {
    int i = blockIdx.x * blockDim.x + threadIdx.x;
    if (i < Nn) g_dinv[i] = 1.0f;
    if (i < 4)  g_acc[i] = 0.f;
}
__global__ void k_deg(const int* __restrict__ ei, const float* __restrict__ w) {
    int e = blockIdx.x * blockDim.x + threadIdx.x;
    if (e < Ee) atomicAdd(&g_dinv[ei[Ee + e]], w[e]);
}
__global__ void k_dinv() {
    int i = blockIdx.x * blockDim.x + threadIdx.x;
    if (i < Nn) g_dinv[i] = rsqrtf(g_dinv[i]);
}

// ---------------- K1: x@W1 partials, 8x5 register tile, split-K x4 ----------------
// grid (79, 4): blockIdx.x = 128-row tile, blockIdx.y = K quarter (500)
// block 160 = 16 rowthr x 10 colthr; thread = 8 rows x 5 pairs
#define KT 20
__global__ __launch_bounds__(160, 3) void k_gemm1(const float* __restrict__ x,
                                                  const float* __restrict__ W1) {
    __shared__ ull xs[KT][128];
    __shared__ ull ws[KT][50];
    const int tid = threadIdx.x;
    const int ct  = tid % 10;       // 5 pairs each
    const int rt  = tid / 10;       // 8 rows each (strided: rt + 16*i)
    const int rowbase = blockIdx.x * 128;
    const int kbase   = blockIdx.y * 500;

    ull acc[8][5];
#pragma unroll
    for (int i = 0; i < 8; i++)
#pragma unroll
        for (int q = 0; q < 5; q++) acc[i][q] = 0ull;

    const ull* w1u = (const ull*)W1;

    for (int kt = 0; kt < 500; kt += KT) {
        const int k0 = kbase + kt;
        // x tile: 128 rows x KT floats = 640 float4
#pragma unroll
        for (int t = 0; t < 4; t++) {
            int idx = tid + t * 160;
            int row = idx / 5, f4 = idx % 5;
            int rg = min(rowbase + row, Nn - 1);
            float4 v = *(const float4*)(x + (size_t)rg * Pp + k0 + f4 * 4);
            xs[f4 * 4 + 0][row] = pack2(v.x, v.x);
            xs[f4 * 4 + 1][row] = pack2(v.y, v.y);
            xs[f4 * 4 + 2][row] = pack2(v.z, v.z);
            xs[f4 * 4 + 3][row] = pack2(v.w, v.w);
        }
        // W tile: KT x 50 ull = 1000
#pragma unroll
        for (int t = 0; t < 7; t++) {
            int idx = tid + t * 160;
            if (idx < KT * 50) {
                int kk = idx / 50, j = idx % 50;
                ws[kk][j] = w1u[(size_t)(k0 + kk) * 50 + j];
            }
        }
        __syncthreads();
#pragma unroll
        for (int kk = 0; kk < KT; kk++) {
            ull xr[8], wr[5];
#pragma unroll
            for (int i = 0; i < 8; i++) xr[i] = xs[kk][rt + 16 * i];
#pragma unroll
            for (int q = 0; q < 5; q++) wr[q] = ws[kk][ct * 5 + q];
#pragma unroll
            for (int i = 0; i < 8; i++)
#pragma unroll
                for (int q = 0; q < 5; q++) fma2(acc[i][q], xr[i], wr[q]);
        }
        __syncthreads();
    }
    ull* outp = g_h1p[blockIdx.y];
#pragma unroll
    for (int i = 0; i < 8; i++) {
        int r = rowbase + rt + 16 * i;
        if (r < Nn) {
#pragma unroll
            for (int q = 0; q < 5; q++)
                outp[(size_t)r * 50 + ct * 5 + q] = acc[i][q];
        }
    }
}

// ---------------- K2: feat_x = celu(celu(sum partials + b1) @ W2 + b2) ----------------
__global__ void k_dae2(const float* __restrict__ b1,
                       const float* __restrict__ W2, const float* __restrict__ b2) {
    int n = blockIdx.x * blockDim.x + threadIdx.x;
    if (n >= Nn) return;
    float xr[DAE0];
#pragma unroll
    for (int j = 0; j < 50; j++) {
        float2 a = unpack2(g_h1p[0][(size_t)n * 50 + j]);
        float2 b = unpack2(g_h1p[1][(size_t)n * 50 + j]);
        float2 c = unpack2(g_h1p[2][(size_t)n * 50 + j]);
        float2 d = unpack2(g_h1p[3][(size_t)n * 50 + j]);
        xr[2*j]   = celu1(a.x + b.x + c.x + d.x + b1[2*j]);
        xr[2*j+1] = celu1(a.y + b.y + c.y + d.y + b1[2*j+1]);
    }
    float acc[DAE1];
#pragma unroll
    for (int j = 0; j < DAE1; j++) acc[j] = b2[j];
    for (int k = 0; k < DAE0; k++) {
        float xv = xr[k];
        const float4* wp = (const float4*)(W2 + k * DAE1);
#pragma unroll
        for (int q = 0; q < 5; q++) {
            float4 w = wp[q];
            acc[4*q]   += xv * w.x; acc[4*q+1] += xv * w.y;
            acc[4*q+2] += xv * w.z; acc[4*q+3] += xv * w.w;
        }
    }
#pragma unroll
    for (int j = 0; j < DAE1; j++) {
        float v = celu1(acc[j]);
        g_feat[(size_t)n * FCAT + j] = v;
        g_fdup[(size_t)n * FCAT + j] = pack2(v, v);
    }
}

// ---------------- K3: hf = feat_x @ Wf ; aggf seeded with self-loop ----------------
__global__ void k_gcnf_lin(const float* __restrict__ Wf, const float* __restrict__ bf) {
    int n = blockIdx.x * blockDim.x + threadIdx.x;
    if (n >= Nn) return;
    float fr[DAE1];
    const float4* fp = (const float4*)(g_feat + (size_t)n * FCAT);
#pragma unroll
    for (int q = 0; q < 5; q++) {
        float4 v = fp[q];
        fr[4*q] = v.x; fr[4*q+1] = v.y; fr[4*q+2] = v.z; fr[4*q+3] = v.w;
    }
    float acc[GAE0];
#pragma unroll
    for (int j = 0; j < GAE0; j++) acc[j] = 0.f;
#pragma unroll
    for (int k = 0; k < DAE1; k++) {
        float xv = fr[k];
        const float4* wp = (const float4*)(Wf + k * GAE0);
#pragma unroll
        for (int q = 0; q < 8; q++) {
            float4 w = wp[q];
            acc[4*q]   += xv * w.x; acc[4*q+1] += xv * w.y;
            acc[4*q+2] += xv * w.z; acc[4*q+3] += xv * w.w;
        }
    }
    float d = g_dinv[n], d2 = d * d;
#pragma unroll
    for (int j = 0; j < GAE0; j++) {
        g_hf  [(size_t)n * GAE0 + j] = acc[j];
        g_aggf[(size_t)n * GAE0 + j] = d2 * acc[j] + bf[j];
    }
}

// ---------------- K4: edge scatter for conv_f (32 dims) ----------------
__global__ void k_edge_f(const int* __restrict__ ei, const float* __restrict__ w) {
    int e = blockIdx.x * blockDim.x + threadIdx.x;
    if (e >= Ee) return;
    int s = ei[e], d = ei[Ee + e];
    float coef = g_dinv[s] * g_dinv[d] * w[e];
    const float4* hp = (const float4*)(g_hf + (size_t)s * GAE0);
    float4* op = (float4*)(g_aggf + (size_t)d * GAE0);
#pragma unroll
    for (int q = 0; q < 8; q++) {
        float4 v = hp[q];
        atomicAdd(op + q, make_float4(coef*v.x, coef*v.y, coef*v.z, coef*v.w));
    }
}

// ---------------- K5: hm = relu(aggf) @ [Wm|Ws] ----------------
__global__ void k_gcnm_lin(const float* __restrict__ Wm, const float* __restrict__ bm,
                           const float* __restrict__ Ws, const float* __restrict__ bs) {
    int n = blockIdx.x * blockDim.x + threadIdx.x;
    if (n >= Nn) return;
    float hr[GAE0];
    const float4* hp = (const float4*)(g_aggf + (size_t)n * GAE0);
#pragma unroll
    for (int q = 0; q < 8; q++) {
        float4 v = hp[q];
        hr[4*q]   = fmaxf(v.x, 0.f); hr[4*q+1] = fmaxf(v.y, 0.f);
        hr[4*q+2] = fmaxf(v.z, 0.f); hr[4*q+3] = fmaxf(v.w, 0.f);
    }
    float am[GAE1], as_[GAE1];
#pragma unroll
    for (int j = 0; j < GAE1; j++) { am[j] = 0.f; as_[j] = 0.f; }
#pragma unroll
    for (int k = 0; k < GAE0; k++) {
        float h = hr[k];
        const float4* wmp = (const float4*)(Wm + k * GAE1);
        const float4* wsp = (const float4*)(Ws + k * GAE1);
#pragma unroll
        for (int q = 0; q < 5; q++) {
            float4 a = wmp[q], b = wsp[q];
            am[4*q]   += h*a.x; am[4*q+1] += h*a.y; am[4*q+2] += h*a.z; am[4*q+3] += h*a.w;
            as_[4*q]  += h*b.x; as_[4*q+1]+= h*b.y; as_[4*q+2]+= h*b.z; as_[4*q+3]+= h*b.w;
        }
    }
    float d = g_dinv[n], d2 = d * d;
#pragma unroll
    for (int j = 0; j < GAE1; j++) {
        g_hm  [(size_t)n * 40 + j]      = am[j];
        g_hm  [(size_t)n * 40 + 20 + j] = as_[j];
        g_aggm[(size_t)n * 40 + j]      = d2 * am[j]  + bm[j];
        g_aggm[(size_t)n * 40 + 20 + j] = d2 * as_[j] + bs[j];
    }
}

// ---------------- K6: edge scatter for mu/logstd (40 dims) ----------------
__global__ void k_edge_m(const int* __restrict__ ei, const float* __restrict__ w) {
    int e = blockIdx.x * blockDim.x + threadIdx.x;
    if (e >= Ee) return;
    int s = ei[e], d = ei[Ee + e];
    float coef = g_dinv[s] * g_dinv[d] * w[e];
    const float4* hp = (const float4*)(g_hm + (size_t)s * 40);
    float4* op = (float4*)(g_aggm + (size_t)d * 40);
#pragma unroll
    for (int q = 0; q < 10; q++) {
        float4 v = hp[q];
        atomicAdd(op + q, make_float4(coef*v.x, coef*v.y, coef*v.z, coef*v.w));
    }
}

// ---------------- K7: z / feat / kl / ct / zg per node ----------------
__global__ void k_node(const float* __restrict__ eps,
                       const float* __restrict__ Wc, const float* __restrict__ bc,
                       const float* __restrict__ Wg, const float* __restrict__ bg,
                       float* __restrict__ out) {
    int n = blockIdx.x * blockDim.x + threadIdx.x;
    float kl = 0.f;
    if (n < Nn) {
        float fr[FCAT];
#pragma unroll
        for (int j = 0; j < DAE1; j++) fr[j] = g_feat[(size_t)n * FCAT + j];
#pragma unroll
        for (int j = 0; j < GAE1; j++) {
            float mu = g_aggm[(size_t)n * 40 + j];
            float ls = fminf(g_aggm[(size_t)n * 40 + 20 + j], 10.0f);
            float z  = mu + eps[(size_t)n * GAE1 + j] * expf(ls);
            kl += 1.f + 2.f * ls - mu * mu - expf(2.f * ls);
            fr[20 + j] = z;
            g_feat[(size_t)n * FCAT + 20 + j] = z;
            g_fdup[(size_t)n * FCAT + 20 + j] = pack2(z, z);
        }
        float c[CTn];
#pragma unroll
        for (int t = 0; t < CTn; t++) c[t] = bc[t];
#pragma unroll
        for (int k = 0; k < FCAT; k++) {
            float f = fr[k];
#pragma unroll
            for (int t = 0; t < CTn; t++) c[t] += f * Wc[k * CTn + t];
        }
        float sum = 0.f;
#pragma unroll
        for (int t = 0; t < CTn; t++) { c[t] = fmaxf(c[t], 0.f); sum += c[t]; }
        float inv = 1.f / (sum + 1e-6f);
#pragma unroll
        for (int t = 0; t < CTn; t++) out[(size_t)n * CTn + t] = c[t] * inv;
        float g[FEATn];
#pragma unroll
        for (int j = 0; j < FEATn; j++) g[j] = bg[j];
#pragma unroll
        for (int k = 0; k < FCAT; k++) {
            float f = fr[k];
            const float4* wp = (const float4*)(Wg + k * FEATn);
#pragma unroll
            for (int q = 0; q < 16; q++) {
                float4 w = wp[q];
                g[4*q]   += f*w.x; g[4*q+1] += f*w.y; g[4*q+2] += f*w.z; g[4*q+3] += f*w.w;
            }
        }
#pragma unroll
        for (int j = 0; j < FEATn; j++) g_zg[(size_t)n * FEATn + j] = fmaxf(g[j], 0.f);
    }
#pragma unroll
    for (int off = 16; off > 0; off >>= 1) kl += __shfl_down_sync(0xffffffffu, kl, off);
    if ((threadIdx.x & 31) == 0) atomicAdd(&g_acc[2], kl);
}

// ---------------- K8: pos/neg edge losses ----------------
__global__ void k_loss(const int* __restrict__ ei, const int* __restrict__ nei,
                       const float* __restrict__ w) {
    int e = blockIdx.x * blockDim.x + threadIdx.x;
    int set = blockIdx.y;
    float v = 0.f;
    if (e < Ee) {
        const int* idx = set ? nei : ei;
        int s = idx[e], d = idx[Ee + e];
        const float4* a = (const float4*)(g_zg + (size_t)s * FEATn);
        const float4* b = (const float4*)(g_zg + (size_t)d * FEATn);
        float dot = 0.f;
#pragma unroll
        for (int q = 0; q < 16; q++) {
            float4 av = a[q], bv = b[q];
            dot += av.x*bv.x + av.y*bv.y + av.z*bv.z + av.w*bv.w;
        }
        float p = 1.f / (1.f + expf(-dot));
        float t = set ? p : (p - w[e]);
        v = t * t;
    }
#pragma unroll
    for (int off = 16; off > 0; off >>= 1) v += __shfl_down_sync(0xffffffffu, v, off);
    if ((threadIdx.x & 31) == 0) atomicAdd(&g_acc[set], v);
}

__global__ void k_final(float* __restrict__ out) {
    out[20100000] = g_acc[0] / (float)Ee + g_acc[1] / (float)Ee
                  - 0.5f * g_acc[2] / ((float)Nn * (float)Nn);
}

// ---------------- K10: x_dec = feat @ Wdec + bdec ----------------
__global__ __launch_bounds__(256) void k_xdec(const float* __restrict__ Wdec,
                                              const float* __restrict__ bdec,
                                              float* __restrict__ out) {
    __shared__ ull sf[16 * FCAT];
    const int tid = threadIdx.x;
    const int s0 = blockIdx.y * 16;
    for (int idx = tid; idx < 16 * FCAT; idx += 256) {
        int n = min(s0 + idx / FCAT, Nn - 1);
        sf[idx] = g_fdup[(size_t)n * FCAT + idx % FCAT];
    }
    __syncthreads();
    int cp = blockIdx.x * 256 + tid;
    if (cp >= Pp / 2) return;
    const ull* wp = (const ull*)Wdec;
    ull bias = ((const ull*)bdec)[cp];
    ull acc[16];
#pragma unroll
    for (int s = 0; s < 16; s++) acc[s] = bias;
#pragma unroll 4
    for (int k = 0; k < FCAT; k++) {
        ull wv = wp[k * (Pp / 2) + cp];
#pragma unroll
        for (int s = 0; s < 16; s++) fma2(acc[s], sf[s * FCAT + k], wv);
    }
#pragma unroll
    for (int s = 0; s < 16; s++) {
        int n = s0 + s;
        if (n < Nn) *(ull*)(out + 100000 + (size_t)n * Pp + 2 * cp) = acc[s];
    }
}

// ---------------- K11: pw head, smem-staged weights + coalesced stores ----------------
// grid (32, 313), block 256 = 64 proteins x 4 spot-groups (8 spots each)
#define KTW 8
__global__ __launch_bounds__(256, 2) void k_pw(const float* __restrict__ Wv,
                                               const float* __restrict__ bv,
                                               float* __restrict__ out) {
    __shared__ ull   sf[32 * FCAT];        // feat pairs, 10KB
    __shared__ float swf[KTW][640];        // weight chunk, 20KB
    __shared__ float sbuf[4][640];         // store staging, 10KB
    const int tid = threadIdx.x;
    const int s0 = blockIdx.y * 32;
    for (int idx = tid; idx < 32 * FCAT; idx += 256) {
        int n = min(s0 + idx / FCAT, Nn - 1);
        sf[idx] = g_fdup[(size_t)n * FCAT + idx % FCAT];
    }
    const int plocal = tid & 63;
    const int p0 = blockIdx.x * 64;
    const int p  = p0 + plocal;
    const int pc = min(p, Pp - 1);
    const int sg = tid >> 6;
    const int pcount = min(64, Pp - p0);
    const ull* bvp = (const ull*)bv;
    ull acc[8][5];
    {
        ull b0 = bvp[5*pc], b1 = bvp[5*pc+1], b2 = bvp[5*pc+2], b3 = bvp[5*pc+3], b4 = bvp[5*pc+4];
#pragma unroll
        for (int s = 0; s < 8; s++) {
            acc[s][0] = b0; acc[s][1] = b1; acc[s][2] = b2; acc[s][3] = b3; acc[s][4] = b4;
        }
    }
    for (int k0 = 0; k0 < FCAT; k0 += KTW) {
        __syncthreads();
        // stage KTW x 640 weights, coalesced: 1280 float4 over 256 threads
#pragma unroll
        for (int t = 0; t < 5; t++) {
            int idx = tid + t * 256;
            int kk = idx / 160, j = idx % 160;
            int gcol = p0 * 10 + j * 4;
            if (gcol > Pp * CTn - 4) gcol = Pp * CTn - 4;
            float4 v = *(const float4*)(Wv + (size_t)(k0 + kk) * (Pp * CTn) + gcol);
            *(float4*)&swf[kk][j * 4] = v;
        }
        __syncthreads();
#pragma unroll
        for (int kk = 0; kk < KTW; kk++) {
            ull wv[5];
            const ull* swu = (const ull*)swf[kk];
#pragma unroll
            for (int q = 0; q < 5; q++) wv[q] = swu[plocal * 5 + q];
#pragma unroll
            for (int s = 0; s < 8; s++) {
                ull f = sf[(sg * 8 + s) * FCAT + k0 + kk];
#pragma unroll
                for (int q = 0; q < 5; q++) fma2(acc[s][q], f, wv[q]);
            }
        }
    }
    // relu + rownorm, stage per spot in smem, then coalesced copy
#pragma unroll
    for (int s = 0; s < 8; s++) {
        __syncthreads();
        {
            float v[CTn];
            float sum = 0.f;
#pragma unroll
            for (int q = 0; q < 5; q++) {
                float2 u = unpack2(acc[s][q]);
                v[2*q]   = fmaxf(u.x, 0.f);
                v[2*q+1] = fmaxf(u.y, 0.f);
                sum += v[2*q] + v[2*q+1];
            }
            float inv = 1.f / (sum + 1e-6f);
#pragma unroll
            for (int c = 0; c < CTn; c++) sbuf[sg][plocal * CTn + c] = v[c] * inv;
        }
        __syncthreads();
        int n = s0 + sg * 8 + s;
        if (n < Nn) {
            // pw base = 100000 + 20000000 + 1 = 20100001 (odd)
            float* o = out + 20100001LL + (size_t)n * (Pp * CTn) + (size_t)p0 * CTn;
            int cnt = pcount * CTn;
#pragma unroll
            for (int j = plocal; j < cnt; j += 64) o[j] = sbuf[sg][j];
        }
    }
}

// ---------------- launch ----------------
extern "C" void kernel_launch(void* const* d_in, const int* in_sizes, int n_in,
                              void* d_out, int out_size) {
    const float* x    = (const float*)d_in[0];
    const float* ew   = (const float*)d_in[1];
    const float* eps  = (const float*)d_in[2];
    const float* W1   = (const float*)d_in[3];
    const float* b1   = (const float*)d_in[4];
    const float* W2   = (const float*)d_in[5];
    const float* b2   = (const float*)d_in[6];
    const float* Wf   = (const float*)d_in[7];
    const float* bf   = (const float*)d_in[8];
    const float* Wm   = (const float*)d_in[9];
    const float* bm   = (const float*)d_in[10];
    const float* Ws   = (const float*)d_in[11];
    const float* bs   = (const float*)d_in[12];
    const float* Wdec = (const float*)d_in[13];
    const float* bdec = (const float*)d_in[14];
    const float* Wg   = (const float*)d_in[15];
    const float* bg   = (const float*)d_in[16];
    const float* Wc   = (const float*)d_in[17];
    const float* bc   = (const float*)d_in[18];
    const float* Wv   = (const float*)d_in[19];
    const float* bv   = (const float*)d_in[20];
    const int*   ei   = (const int*)d_in[21];
    const int*   nei  = (const int*)d_in[22];
    float* out = (float*)d_out;

    k_init <<<(Nn + 255) / 256, 256>>>();
    k_deg  <<<Ee / 256, 256>>>(ei, ew);
    k_dinv <<<(Nn + 255) / 256, 256>>>();
    k_gemm1<<<dim3((Nn + 127) / 128, 4), 160>>>(x, W1);
    k_dae2 <<<(Nn + 127) / 128, 128>>>(b1, W2, b2);
    k_gcnf_lin<<<(Nn + 127) / 128, 128>>>(Wf, bf);
    k_edge_f  <<<Ee / 128, 128>>>(ei, ew);
    k_gcnm_lin<<<(Nn + 127) / 128, 128>>>(Wm, bm, Ws, bs);
    k_edge_m  <<<Ee / 128, 128>>>(ei, ew);
    k_node <<<(Nn + 127) / 128, 128>>>(eps, Wc, bc, Wg, bg, out);
    k_loss <<<dim3(Ee / 256, 2), 256>>>(ei, nei, ew);
    k_final<<<1, 1>>>(out);
    k_xdec <<<dim3(4, (Nn + 15) / 16), 256>>>(Wdec, bdec, out);
    k_pw   <<<dim3((Pp + 63) / 64, (Nn + 31) / 32), 256>>>(Wv, bv, out);
}

// round 4
// speedup vs baseline: 1.0710x; 1.0710x over previous
#include <cuda_runtime.h>
#include <cstdint>

#define Nn    10000
#define Pp    2000
#define CTn   10
#define Ee    320000
#define DAE0  100
#define DAE1  20
#define GAE0  32
#define GAE1  20
#define FCAT  40
#define FEATn 64

typedef unsigned long long ull;

__device__ __forceinline__ void fma2(ull &d, ull a, ull b) {
    asm("fma.rn.f32x2 %0, %1, %2, %0;" : "+l"(d) : "l"(a), "l"(b));
}
__device__ __forceinline__ ull pack2(float a, float b) {
    ull r; asm("mov.b64 %0, {%1,%2};" : "=l"(r) : "f"(a), "f"(b)); return r;
}
__device__ __forceinline__ float2 unpack2(ull v) {
    float2 r; asm("mov.b64 {%0,%1}, %2;" : "=f"(r.x), "=f"(r.y) : "l"(v)); return r;
}
__device__ __forceinline__ float celu1(float x) { return x > 0.f ? x : expm1f(x); }

__device__ float g_dinv[Nn];
__device__ ull   g_h1p[4][Nn * 50];
__device__ float g_feat[Nn * FCAT];
__device__ ull   g_fdup[Nn * FCAT];
__device__ float g_hf  [Nn * GAE0];
__device__ float g_aggf[Nn * GAE0];
__device__ float g_hm  [Nn * 2 * GAE1];
__device__ float g_aggm[Nn * 2 * GAE1];
__device__ float g_zg  [Nn * FEATn];
__device__ float g_acc [4];
__device__ ull   g_wvt [FCAT * 5 * Pp];   // [(k*5+q)][p], p in [0,2000)

__global__ void k_init() {
    int i = blockIdx.x * blockDim.x + threadIdx.x;
    if (i < Nn) g_dinv[i] = 1.0f;
    if (i < 4)  g_acc[i] = 0.f;
}
__global__ void k_deg(const int* __restrict__ ei, const float* __restrict__ w) {
    int e = blockIdx.x * blockDim.x + threadIdx.x;
    if (e < Ee) atomicAdd(&g_dinv[ei[Ee + e]], w[e]);
}
__global__ void k_dinv() {
    int i = blockIdx.x * blockDim.x + threadIdx.x;
    if (i < Nn) g_dinv[i] = rsqrtf(g_dinv[i]);
}

// transpose Wv (40 x 20000 floats = 40 x 10000 ull) into [(k*5+q)][p]
__global__ void k_wvt(const float* __restrict__ Wv) {
    int i = blockIdx.x * blockDim.x + threadIdx.x;   // 400000 ulls
    if (i >= FCAT * Pp * 5) return;
    int k = i / (Pp * 5), j = i % (Pp * 5);
    int p = j / 5, q = j % 5;
    g_wvt[(size_t)(k * 5 + q) * Pp + p] = ((const ull*)Wv)[i];
}

#define KT 20
__global__ __launch_bounds__(160, 4) void k_gemm1(const float* __restrict__ x,
                                                  const float* __restrict__ W1) {
    __shared__ ull xs[KT][64];
    __shared__ ull ws[KT][50];
    const int tid = threadIdx.x;
    const int ct  = tid % 10;
    const int rt  = tid / 10;
    const int rowbase = blockIdx.x * 64;
    const int kbase   = blockIdx.y * 500;

    ull acc[4][5];
#pragma unroll
    for (int i = 0; i < 4; i++)
#pragma unroll
        for (int q = 0; q < 5; q++) acc[i][q] = 0ull;

    const ull* w1u = (const ull*)W1;

    for (int kt = 0; kt < 500; kt += KT) {
        const int k0 = kbase + kt;
#pragma unroll
        for (int t = 0; t < 2; t++) {
            int idx = tid + t * 160;
            int row = idx / 5, f4 = idx % 5;
            int rg = min(rowbase + row, Nn - 1);
            float4 v = *(const float4*)(x + (size_t)rg * Pp + k0 + f4 * 4);
            xs[f4 * 4 + 0][row] = pack2(v.x, v.x);
            xs[f4 * 4 + 1][row] = pack2(v.y, v.y);
            xs[f4 * 4 + 2][row] = pack2(v.z, v.z);
            xs[f4 * 4 + 3][row] = pack2(v.w, v.w);
        }
#pragma unroll
        for (int t = 0; t < 7; t++) {
            int idx = tid + t * 160;
            if (idx < KT * 50) {
                int kk = idx / 50, j = idx % 50;
                ws[kk][j] = w1u[(size_t)(k0 + kk) * 50 + j];
            }
        }
        __syncthreads();
#pragma unroll
        for (int kk = 0; kk < KT; kk++) {
            ull xr[4], wr[5];
#pragma unroll
            for (int i = 0; i < 4; i++) xr[i] = xs[kk][rt * 4 + i];
#pragma unroll
            for (int q = 0; q < 5; q++) wr[q] = ws[kk][ct * 5 + q];
#pragma unroll
            for (int i = 0; i < 4; i++)
#pragma unroll
                for (int q = 0; q < 5; q++) fma2(acc[i][q], xr[i], wr[q]);
        }
        __syncthreads();
    }
    ull* outp = g_h1p[blockIdx.y];
#pragma unroll
    for (int i = 0; i < 4; i++) {
        int r = rowbase + rt * 4 + i;
        if (r < Nn) {
#pragma unroll
            for (int q = 0; q < 5; q++)
                outp[(size_t)r * 50 + ct * 5 + q] = acc[i][q];
        }
    }
}

__global__ void k_dae2(const float* __restrict__ b1,
                       const float* __restrict__ W2, const float* __restrict__ b2) {
    int n = blockIdx.x * blockDim.x + threadIdx.x;
    if (n >= Nn) return;
    float xr[DAE0];
#pragma unroll
    for (int j = 0; j < 50; j++) {
        float2 a = unpack2(g_h1p[0][(size_t)n * 50 + j]);
        float2 b = unpack2(g_h1p[1][(size_t)n * 50 + j]);
        float2 c = unpack2(g_h1p[2][(size_t)n * 50 + j]);
        float2 d = unpack2(g_h1p[3][(size_t)n * 50 + j]);
        xr[2*j]   = celu1(a.x + b.x + c.x + d.x + b1[2*j]);
        xr[2*j+1] = celu1(a.y + b.y + c.y + d.y + b1[2*j+1]);
    }
    float acc[DAE1];
#pragma unroll
    for (int j = 0; j < DAE1; j++) acc[j] = b2[j];
    for (int k = 0; k < DAE0; k++) {
        float xv = xr[k];
        const float4* wp = (const float4*)(W2 + k * DAE1);
#pragma unroll
        for (int q = 0; q < 5; q++) {
            float4 w = wp[q];
            acc[4*q]   += xv * w.x; acc[4*q+1] += xv * w.y;
            acc[4*q+2] += xv * w.z; acc[4*q+3] += xv * w.w;
        }
    }
#pragma unroll
    for (int j = 0; j < DAE1; j++) {
        float v = celu1(acc[j]);
        g_feat[(size_t)n * FCAT + j] = v;
        g_fdup[(size_t)n * FCAT + j] = pack2(v, v);
    }
}

__global__ void k_gcnf_lin(const float* __restrict__ Wf, const float* __restrict__ bf) {
    int n = blockIdx.x * blockDim.x + threadIdx.x;
    if (n >= Nn) return;
    float fr[DAE1];
    const float4* fp = (const float4*)(g_feat + (size_t)n * FCAT);
#pragma unroll
    for (int q = 0; q < 5; q++) {
        float4 v = fp[q];
        fr[4*q] = v.x; fr[4*q+1] = v.y; fr[4*q+2] = v.z; fr[4*q+3] = v.w;
    }
    float acc[GAE0];
#pragma unroll
    for (int j = 0; j < GAE0; j++) acc[j] = 0.f;
#pragma unroll
    for (int k = 0; k < DAE1; k++) {
        float xv = fr[k];
        const float4* wp = (const float4*)(Wf + k * GAE0);
#pragma unroll
        for (int q = 0; q < 8; q++) {
            float4 w = wp[q];
            acc[4*q]   += xv * w.x; acc[4*q+1] += xv * w.y;
            acc[4*q+2] += xv * w.z; acc[4*q+3] += xv * w.w;
        }
    }
    float d = g_dinv[n], d2 = d * d;
#pragma unroll
    for (int j = 0; j < GAE0; j++) {
        g_hf  [(size_t)n * GAE0 + j] = acc[j];
        g_aggf[(size_t)n * GAE0 + j] = d2 * acc[j] + bf[j];
    }
}

__global__ void k_edge_f(const int* __restrict__ ei, const float* __restrict__ w) {
    int e = blockIdx.x * blockDim.x + threadIdx.x;
    if (e >= Ee) return;
    int s = ei[e], d = ei[Ee + e];
    float coef = g_dinv[s] * g_dinv[d] * w[e];
    const float4* hp = (const float4*)(g_hf + (size_t)s * GAE0);
    float4* op = (float4*)(g_aggf + (size_t)d * GAE0);
#pragma unroll
    for (int q = 0; q < 8; q++) {
        float4 v = hp[q];
        atomicAdd(op + q, make_float4(coef*v.x, coef*v.y, coef*v.z, coef*v.w));
    }
}

__global__ void k_gcnm_lin(const float* __restrict__ Wm, const float* __restrict__ bm,
                           const float* __restrict__ Ws, const float* __restrict__ bs) {
    int n = blockIdx.x * blockDim.x + threadIdx.x;
    if (n >= Nn) return;
    float hr[GAE0];
    const float4* hp = (const float4*)(g_aggf + (size_t)n * GAE0);
#pragma unroll
    for (int q = 0; q < 8; q++) {
        float4 v = hp[q];
        hr[4*q]   = fmaxf(v.x, 0.f); hr[4*q+1] = fmaxf(v.y, 0.f);
        hr[4*q+2] = fmaxf(v.z, 0.f); hr[4*q+3] = fmaxf(v.w, 0.f);
    }
    float am[GAE1], as_[GAE1];
#pragma unroll
    for (int j = 0; j < GAE1; j++) { am[j] = 0.f; as_[j] = 0.f; }
#pragma unroll
    for (int k = 0; k < GAE0; k++) {
        float h = hr[k];
        const float4* wmp = (const float4*)(Wm + k * GAE1);
        const float4* wsp = (const float4*)(Ws + k * GAE1);
#pragma unroll
        for (int q = 0; q < 5; q++) {
            float4 a = wmp[q], b = wsp[q];
            am[4*q]   += h*a.x; am[4*q+1] += h*a.y; am[4*q+2] += h*a.z; am[4*q+3] += h*a.w;
            as_[4*q]  += h*b.x; as_[4*q+1]+= h*b.y; as_[4*q+2]+= h*b.z; as_[4*q+3]+= h*b.w;
        }
    }
    float d = g_dinv[n], d2 = d * d;
#pragma unroll
    for (int j = 0; j < GAE1; j++) {
        g_hm  [(size_t)n * 40 + j]      = am[j];
        g_hm  [(size_t)n * 40 + 20 + j] = as_[j];
        g_aggm[(size_t)n * 40 + j]      = d2 * am[j]  + bm[j];
        g_aggm[(size_t)n * 40 + 20 + j] = d2 * as_[j] + bs[j];
    }
}

__global__ void k_edge_m(const int* __restrict__ ei, const float* __restrict__ w) {
    int e = blockIdx.x * blockDim.x + threadIdx.x;
    if (e >= Ee) return;
    int s = ei[e], d = ei[Ee + e];
    float coef = g_dinv[s] * g_dinv[d] * w[e];
    const float4* hp = (const float4*)(g_hm + (size_t)s * 40);
    float4* op = (float4*)(g_aggm + (size_t)d * 40);
#pragma unroll
    for (int q = 0; q < 10; q++) {
        float4 v = hp[q];
        atomicAdd(op + q, make_float4(coef*v.x, coef*v.y, coef*v.z, coef*v.w));
    }
}

__global__ void k_node(const float* __restrict__ eps,
                       const float* __restrict__ Wc, const float* __restrict__ bc,
                       const float* __restrict__ Wg, const float* __restrict__ bg,
                       float* __restrict__ out) {
    int n = blockIdx.x * blockDim.x + threadIdx.x;
    float kl = 0.f;
    if (n < Nn) {
        float fr[FCAT];
#pragma unroll
        for (int j = 0; j < DAE1; j++) fr[j] = g_feat[(size_t)n * FCAT + j];
#pragma unroll
        for (int j = 0; j < GAE1; j++) {
            float mu = g_aggm[(size_t)n * 40 + j];
            float ls = fminf(g_aggm[(size_t)n * 40 + 20 + j], 10.0f);
            float z  = mu + eps[(size_t)n * GAE1 + j] * expf(ls);
            kl += 1.f + 2.f * ls - mu * mu - expf(2.f * ls);
            fr[20 + j] = z;
            g_feat[(size_t)n * FCAT + 20 + j] = z;
            g_fdup[(size_t)n * FCAT + 20 + j] = pack2(z, z);
        }
        float c[CTn];
#pragma unroll
        for (int t = 0; t < CTn; t++) c[t] = bc[t];
#pragma unroll
        for (int k = 0; k < FCAT; k++) {
            float f = fr[k];
#pragma unroll
            for (int t = 0; t < CTn; t++) c[t] += f * Wc[k * CTn + t];
        }
        float sum = 0.f;
#pragma unroll
        for (int t = 0; t < CTn; t++) { c[t] = fmaxf(c[t], 0.f); sum += c[t]; }
        float inv = 1.f / (sum + 1e-6f);
#pragma unroll
        for (int t = 0; t < CTn; t++) out[(size_t)n * CTn + t] = c[t] * inv;
        float g[FEATn];
#pragma unroll
        for (int j = 0; j < FEATn; j++) g[j] = bg[j];
#pragma unroll
        for (int k = 0; k < FCAT; k++) {
            float f = fr[k];
            const float4* wp = (const float4*)(Wg + k * FEATn);
#pragma unroll
            for (int q = 0; q < 16; q++) {
                float4 w = wp[q];
                g[4*q]   += f*w.x; g[4*q+1] += f*w.y; g[4*q+2] += f*w.z; g[4*q+3] += f*w.w;
            }
        }
#pragma unroll
        for (int j = 0; j < FEATn; j++) g_zg[(size_t)n * FEATn + j] = fmaxf(g[j], 0.f);
    }
#pragma unroll
    for (int off = 16; off > 0; off >>= 1) kl += __shfl_down_sync(0xffffffffu, kl, off);
    if ((threadIdx.x & 31) == 0) atomicAdd(&g_acc[2], kl);
}

__global__ void k_loss(const int* __restrict__ ei, const int* __restrict__ nei,
                       const float* __restrict__ w) {
    int e = blockIdx.x * blockDim.x + threadIdx.x;
    int set = blockIdx.y;
    float v = 0.f;
    if (e < Ee) {
        const int* idx = set ? nei : ei;
        int s = idx[e], d = idx[Ee + e];
        const float4* a = (const float4*)(g_zg + (size_t)s * FEATn);
        const float4* b = (const float4*)(g_zg + (size_t)d * FEATn);
        float dot = 0.f;
#pragma unroll
        for (int q = 0; q < 16; q++) {
            float4 av = a[q], bv = b[q];
            dot += av.x*bv.x + av.y*bv.y + av.z*bv.z + av.w*bv.w;
        }
        float p = 1.f / (1.f + expf(-dot));
        float t = set ? p : (p - w[e]);
        v = t * t;
    }
#pragma unroll
    for (int off = 16; off > 0; off >>= 1) v += __shfl_down_sync(0xffffffffu, v, off);
    if ((threadIdx.x & 31) == 0) atomicAdd(&g_acc[set], v);
}

__global__ void k_final(float* __restrict__ out) {
    out[20100000] = g_acc[0] / (float)Ee + g_acc[1] / (float)Ee
                  - 0.5f * g_acc[2] / ((float)Nn * (float)Nn);
}

__global__ __launch_bounds__(256) void k_xdec(const float* __restrict__ Wdec,
                                              const float* __restrict__ bdec,
                                              float* __restrict__ out) {
    __shared__ ull sf[16 * FCAT];
    const int tid = threadIdx.x;
    const int s0 = blockIdx.y * 16;
    for (int idx = tid; idx < 16 * FCAT; idx += 256) {
        int n = min(s0 + idx / FCAT, Nn - 1);
        sf[idx] = g_fdup[(size_t)n * FCAT + idx % FCAT];
    }
    __syncthreads();
    int cp = blockIdx.x * 256 + tid;
    if (cp >= Pp / 2) return;
    const ull* wp = (const ull*)Wdec;
    ull bias = ((const ull*)bdec)[cp];
    ull acc[16];
#pragma unroll
    for (int s = 0; s < 16; s++) acc[s] = bias;
#pragma unroll 4
    for (int k = 0; k < FCAT; k++) {
        ull wv = wp[k * (Pp / 2) + cp];
#pragma unroll
        for (int s = 0; s < 16; s++) fma2(acc[s], sf[s * FCAT + k], wv);
    }
#pragma unroll
    for (int s = 0; s < 16; s++) {
        int n = s0 + s;
        if (n < Nn) *(ull*)(out + 100000 + (size_t)n * Pp + 2 * cp) = acc[s];
    }
}

// pw head: transposed weights (coalesced LDG.64) + smem-staged coalesced stores
__global__ __launch_bounds__(256, 2) void k_pw(const float* __restrict__ bv,
                                               float* __restrict__ out) {
    __shared__ ull   sf[32 * FCAT];
    __shared__ float sbuf[4][640];
    const int tid = threadIdx.x;
    const int s0 = blockIdx.y * 32;
    for (int idx = tid; idx < 32 * FCAT; idx += 256) {
        int n = min(s0 + idx / FCAT, Nn - 1);
        sf[idx] = g_fdup[(size_t)n * FCAT + idx % FCAT];
    }
    __syncthreads();
    const int plocal = tid & 63;
    const int p0 = blockIdx.x * 64;
    const int p  = p0 + plocal;
    const int pc = min(p, Pp - 1);
    const int sg = tid >> 6;
    const int pcount = min(64, Pp - p0);
    const ull* bvp = (const ull*)bv;
    ull acc[8][5];
    {
        ull b0 = bvp[5*pc], b1 = bvp[5*pc+1], b2 = bvp[5*pc+2], b3 = bvp[5*pc+3], b4 = bvp[5*pc+4];
#pragma unroll
        for (int s = 0; s < 8; s++) {
            acc[s][0] = b0; acc[s][1] = b1; acc[s][2] = b2; acc[s][3] = b3; acc[s][4] = b4;
        }
    }
#pragma unroll 4
    for (int k = 0; k < FCAT; k++) {
        ull wv[5];
#pragma unroll
        for (int q = 0; q < 5; q++) wv[q] = g_wvt[(size_t)(k * 5 + q) * Pp + pc];
#pragma unroll
        for (int s = 0; s < 8; s++) {
            ull f = sf[(sg * 8 + s) * FCAT + k];
#pragma unroll
            for (int q = 0; q < 5; q++) fma2(acc[s][q], f, wv[q]);
        }
    }
#pragma unroll
    for (int s = 0; s < 8; s++) {
        {
            float v[CTn];
            float sum = 0.f;
#pragma unroll
            for (int q = 0; q < 5; q++) {
                float2 u = unpack2(acc[s][q]);
                v[2*q]   = fmaxf(u.x, 0.f);
                v[2*q+1] = fmaxf(u.y, 0.f);
                sum += v[2*q] + v[2*q+1];
            }
            float inv = 1.f / (sum + 1e-6f);
#pragma unroll
            for (int c = 0; c < CTn; c++) sbuf[sg][plocal * CTn + c] = v[c] * inv;
        }
        __syncthreads();
        int n = s0 + sg * 8 + s;
        if (n < Nn) {
            float* o = out + 20100001LL + (size_t)n * (Pp * CTn) + (size_t)p0 * CTn;
            int cnt = pcount * CTn;
#pragma unroll
            for (int j = plocal; j < cnt; j += 64) o[j] = sbuf[sg][j];
        }
        __syncthreads();
    }
}

extern "C" void kernel_launch(void* const* d_in, const int* in_sizes, int n_in,
                              void* d_out, int out_size) {
    const float* x    = (const float*)d_in[0];
    const float* ew   = (const float*)d_in[1];
    const float* eps  = (const float*)d_in[2];
    const float* W1   = (const float*)d_in[3];
    const float* b1   = (const float*)d_in[4];
    const float* W2   = (const float*)d_in[5];
    const float* b2   = (const float*)d_in[6];
    const float* Wf   = (const float*)d_in[7];
    const float* bf   = (const float*)d_in[8];
    const float* Wm   = (const float*)d_in[9];
    const float* bm   = (const float*)d_in[10];
    const float* Ws   = (const float*)d_in[11];
    const float* bs   = (const float*)d_in[12];
    const float* Wdec = (const float*)d_in[13];
    const float* bdec = (const float*)d_in[14];
    const float* Wg   = (const float*)d_in[15];
    const float* bg   = (const float*)d_in[16];
    const float* Wc   = (const float*)d_in[17];
    const float* bc   = (const float*)d_in[18];
    const float* Wv   = (const float*)d_in[19];
    const float* bv   = (const float*)d_in[20];
    const int*   ei   = (const int*)d_in[21];
    const int*   nei  = (const int*)d_in[22];
    float* out = (float*)d_out;

    k_init <<<(Nn + 255) / 256, 256>>>();
    k_deg  <<<Ee / 256, 256>>>(ei, ew);
    k_dinv <<<(Nn + 255) / 256, 256>>>();
    k_wvt  <<<(FCAT * Pp * 5 + 255) / 256, 256>>>(Wv);
    k_gemm1<<<dim3((Nn + 63) / 64, 4), 160>>>(x, W1);
    k_dae2 <<<(Nn + 127) / 128, 128>>>(b1, W2, b2);
    k_gcnf_lin<<<(Nn + 127) / 128, 128>>>(Wf, bf);
    k_edge_f  <<<Ee / 128, 128>>>(ei, ew);
    k_gcnm_lin<<<(Nn + 127) / 128, 128>>>(Wm, bm, Ws, bs);
    k_edge_m  <<<Ee / 128, 128>>>(ei, ew);
    k_node <<<(Nn + 127) / 128, 128>>>(eps, Wc, bc, Wg, bg, out);
    k_loss <<<dim3(Ee / 256, 2), 256>>>(ei, nei, ew);
    k_final<<<1, 1>>>(out);
    k_xdec <<<dim3(4, (Nn + 15) / 16), 256>>>(Wdec, bdec, out);
    k_pw   <<<dim3((Pp + 63) / 64, (Nn + 31) / 32), 256>>>(bv, out);
}

// round 5
// speedup vs baseline: 1.1285x; 1.0536x over previous
#include <cuda_runtime.h>
#include <cstdint>

#define Nn    10000
#define Pp    2000
#define CTn   10
#define Ee    320000
#define DAE0  100
#define DAE1  20
#define GAE0  32
#define GAE1  20
#define FCAT  40
#define FEATn 64

typedef unsigned long long ull;

__device__ __forceinline__ void fma2(ull &d, ull a, ull b) {
    asm("fma.rn.f32x2 %0, %1, %2, %0;" : "+l"(d) : "l"(a), "l"(b));
}
__device__ __forceinline__ ull pack2(float a, float b) {
    ull r; asm("mov.b64 %0, {%1,%2};" : "=l"(r) : "f"(a), "f"(b)); return r;
}
__device__ __forceinline__ float2 unpack2(ull v) {
    float2 r; asm("mov.b64 {%0,%1}, %2;" : "=f"(r.x), "=f"(r.y) : "l"(v)); return r;
}
__device__ __forceinline__ float celu1(float x) { return x > 0.f ? x : expm1f(x); }
__device__ __forceinline__ uint32_t s2u(const void* p) {
    return (uint32_t)__cvta_generic_to_shared(p);
}

__device__ float g_dinv[Nn];
__device__ ull   g_h1p[4][Nn * 50];
__device__ float g_feat[Nn * FCAT];
__device__ ull   g_fdup[Nn * FCAT];
__device__ float g_hf  [Nn * GAE0];
__device__ float g_aggf[Nn * GAE0];
__device__ float g_hm  [Nn * 2 * GAE1];
__device__ float g_aggm[Nn * 2 * GAE1];
__device__ float g_zg  [Nn * FEATn];
__device__ float g_acc [4];
__device__ ull   g_wvt [FCAT * 5 * Pp];   // [(k*5+q)][p]

__global__ void k_init() {
    int i = blockIdx.x * blockDim.x + threadIdx.x;
    if (i < Nn) g_dinv[i] = 1.0f;
    if (i < 4)  g_acc[i] = 0.f;
}
__global__ void k_deg(const int* __restrict__ ei, const float* __restrict__ w) {
    int e = blockIdx.x * blockDim.x + threadIdx.x;
    if (e < Ee) atomicAdd(&g_dinv[ei[Ee + e]], w[e]);
}
__global__ void k_dinv() {
    int i = blockIdx.x * blockDim.x + threadIdx.x;
    if (i < Nn) g_dinv[i] = rsqrtf(g_dinv[i]);
}

__global__ void k_wvt(const float* __restrict__ Wv) {
    int i = blockIdx.x * blockDim.x + threadIdx.x;   // 400000 ulls
    if (i >= FCAT * Pp * 5) return;
    int k = i / (Pp * 5), j = i % (Pp * 5);
    int p = j / 5, q = j % 5;
    g_wvt[(size_t)(k * 5 + q) * Pp + p] = ((const ull*)Wv)[i];
}

// ---------------- K1: x@W1 partials, cp.async double-buffered ----------------
// grid (157, 4), block 160 = 16 rowthr x 10 colthr; thread = 4 rows x 5 pairs
#define KT   20
#define XPAD 22
#define NIT  25   // 500 / KT
__global__ __launch_bounds__(160, 4) void k_gemm1(const float* __restrict__ x,
                                                  const float* __restrict__ W1) {
    __shared__ float xs[2][64 * XPAD];
    __shared__ ull   ws[2][KT * 50];
    const int tid = threadIdx.x;
    const int ct  = tid % 10;
    const int rt  = tid / 10;
    const int rowbase = blockIdx.x * 64;
    const int kbase   = blockIdx.y * 500;

    ull acc[4][5];
#pragma unroll
    for (int i = 0; i < 4; i++)
#pragma unroll
        for (int q = 0; q < 5; q++) acc[i][q] = 0ull;

    // async tile loader: x tile 64 rows x KT floats (8B chunks),
    // W tile KT x 50 ull (16B chunks)
#define LOAD_TILE(IT, BUF) do {                                                  \
        const int k0_ = kbase + (IT) * KT;                                       \
        _Pragma("unroll")                                                        \
        for (int t = 0; t < 4; t++) {                                            \
            int idx = tid + t * 160;                                             \
            int row = idx / 10, c = idx % 10;                                    \
            int rg = min(rowbase + row, Nn - 1);                                 \
            const float* src = x + (size_t)rg * Pp + k0_ + c * 2;                \
            uint32_t dst = s2u(&xs[BUF][row * XPAD + c * 2]);                    \
            asm volatile("cp.async.ca.shared.global [%0], [%1], 8;"              \
                         :: "r"(dst), "l"(src));                                 \
        }                                                                        \
        _Pragma("unroll")                                                        \
        for (int t = 0; t < 4; t++) {                                            \
            int idx = tid + t * 160;                                             \
            if (idx < 500) {                                                     \
                int kk = idx / 25, off = idx % 25;                               \
                const float* src = W1 + (size_t)(k0_ + kk) * 100 + off * 4;      \
                uint32_t dst = s2u((const char*)&ws[BUF][kk * 50] + off * 16);   \
                asm volatile("cp.async.ca.shared.global [%0], [%1], 16;"         \
                             :: "r"(dst), "l"(src));                             \
            }                                                                    \
        }                                                                        \
    } while (0)

    LOAD_TILE(0, 0);
    asm volatile("cp.async.commit_group;");

    for (int it = 0; it < NIT; ++it) {
        if (it + 1 < NIT) {
            LOAD_TILE(it + 1, (it + 1) & 1);
            asm volatile("cp.async.commit_group;");
            asm volatile("cp.async.wait_group 1;");
        } else {
            asm volatile("cp.async.wait_group 0;");
        }
        __syncthreads();
        const float* xb = &xs[it & 1][0];
        const ull*   wb = &ws[it & 1][0];
#pragma unroll
        for (int kk = 0; kk < KT; kk++) {
            ull xr[4], wr[5];
#pragma unroll
            for (int i = 0; i < 4; i++) {
                float xv = xb[(rt * 4 + i) * XPAD + kk];
                xr[i] = pack2(xv, xv);
            }
#pragma unroll
            for (int q = 0; q < 5; q++) wr[q] = wb[kk * 50 + ct * 5 + q];
#pragma unroll
            for (int i = 0; i < 4; i++)
#pragma unroll
                for (int q = 0; q < 5; q++) fma2(acc[i][q], xr[i], wr[q]);
        }
        __syncthreads();
    }
#undef LOAD_TILE
    ull* outp = g_h1p[blockIdx.y];
#pragma unroll
    for (int i = 0; i < 4; i++) {
        int r = rowbase + rt * 4 + i;
        if (r < Nn) {
#pragma unroll
            for (int q = 0; q < 5; q++)
                outp[(size_t)r * 50 + ct * 5 + q] = acc[i][q];
        }
    }
}

__global__ void k_dae2(const float* __restrict__ b1,
                       const float* __restrict__ W2, const float* __restrict__ b2) {
    int n = blockIdx.x * blockDim.x + threadIdx.x;
    if (n >= Nn) return;
    float xr[DAE0];
#pragma unroll
    for (int j = 0; j < 50; j++) {
        float2 a = unpack2(g_h1p[0][(size_t)n * 50 + j]);
        float2 b = unpack2(g_h1p[1][(size_t)n * 50 + j]);
        float2 c = unpack2(g_h1p[2][(size_t)n * 50 + j]);
        float2 d = unpack2(g_h1p[3][(size_t)n * 50 + j]);
        xr[2*j]   = celu1(a.x + b.x + c.x + d.x + b1[2*j]);
        xr[2*j+1] = celu1(a.y + b.y + c.y + d.y + b1[2*j+1]);
    }
    float acc[DAE1];
#pragma unroll
    for (int j = 0; j < DAE1; j++) acc[j] = b2[j];
    for (int k = 0; k < DAE0; k++) {
        float xv = xr[k];
        const float4* wp = (const float4*)(W2 + k * DAE1);
#pragma unroll
        for (int q = 0; q < 5; q++) {
            float4 w = wp[q];
            acc[4*q]   += xv * w.x; acc[4*q+1] += xv * w.y;
            acc[4*q+2] += xv * w.z; acc[4*q+3] += xv * w.w;
        }
    }
#pragma unroll
    for (int j = 0; j < DAE1; j++) {
        float v = celu1(acc[j]);
        g_feat[(size_t)n * FCAT + j] = v;
        g_fdup[(size_t)n * FCAT + j] = pack2(v, v);
    }
}

__global__ void k_gcnf_lin(const float* __restrict__ Wf, const float* __restrict__ bf) {
    int n = blockIdx.x * blockDim.x + threadIdx.x;
    if (n >= Nn) return;
    float fr[DAE1];
    const float4* fp = (const float4*)(g_feat + (size_t)n * FCAT);
#pragma unroll
    for (int q = 0; q < 5; q++) {
        float4 v = fp[q];
        fr[4*q] = v.x; fr[4*q+1] = v.y; fr[4*q+2] = v.z; fr[4*q+3] = v.w;
    }
    float acc[GAE0];
#pragma unroll
    for (int j = 0; j < GAE0; j++) acc[j] = 0.f;
#pragma unroll
    for (int k = 0; k < DAE1; k++) {
        float xv = fr[k];
        const float4* wp = (const float4*)(Wf + k * GAE0);
#pragma unroll
        for (int q = 0; q < 8; q++) {
            float4 w = wp[q];
            acc[4*q]   += xv * w.x; acc[4*q+1] += xv * w.y;
            acc[4*q+2] += xv * w.z; acc[4*q+3] += xv * w.w;
        }
    }
    float d = g_dinv[n], d2 = d * d;
#pragma unroll
    for (int j = 0; j < GAE0; j++) {
        g_hf  [(size_t)n * GAE0 + j] = acc[j];
        g_aggf[(size_t)n * GAE0 + j] = d2 * acc[j] + bf[j];
    }
}

__global__ void k_edge_f(const int* __restrict__ ei, const float* __restrict__ w) {
    int e = blockIdx.x * blockDim.x + threadIdx.x;
    if (e >= Ee) return;
    int s = ei[e], d = ei[Ee + e];
    float coef = g_dinv[s] * g_dinv[d] * w[e];
    const float4* hp = (const float4*)(g_hf + (size_t)s * GAE0);
    float4* op = (float4*)(g_aggf + (size_t)d * GAE0);
#pragma unroll
    for (int q = 0; q < 8; q++) {
        float4 v = hp[q];
        atomicAdd(op + q, make_float4(coef*v.x, coef*v.y, coef*v.z, coef*v.w));
    }
}

__global__ void k_gcnm_lin(const float* __restrict__ Wm, const float* __restrict__ bm,
                           const float* __restrict__ Ws, const float* __restrict__ bs) {
    int n = blockIdx.x * blockDim.x + threadIdx.x;
    if (n >= Nn) return;
    float hr[GAE0];
    const float4* hp = (const float4*)(g_aggf + (size_t)n * GAE0);
#pragma unroll
    for (int q = 0; q < 8; q++) {
        float4 v = hp[q];
        hr[4*q]   = fmaxf(v.x, 0.f); hr[4*q+1] = fmaxf(v.y, 0.f);
        hr[4*q+2] = fmaxf(v.z, 0.f); hr[4*q+3] = fmaxf(v.w, 0.f);
    }
    float am[GAE1], as_[GAE1];
#pragma unroll
    for (int j = 0; j < GAE1; j++) { am[j] = 0.f; as_[j] = 0.f; }
#pragma unroll
    for (int k = 0; k < GAE0; k++) {
        float h = hr[k];
        const float4* wmp = (const float4*)(Wm + k * GAE1);
        const float4* wsp = (const float4*)(Ws + k * GAE1);
#pragma unroll
        for (int q = 0; q < 5; q++) {
            float4 a = wmp[q], b = wsp[q];
            am[4*q]   += h*a.x; am[4*q+1] += h*a.y; am[4*q+2] += h*a.z; am[4*q+3] += h*a.w;
            as_[4*q]  += h*b.x; as_[4*q+1]+= h*b.y; as_[4*q+2]+= h*b.z; as_[4*q+3]+= h*b.w;
        }
    }
    float d = g_dinv[n], d2 = d * d;
#pragma unroll
    for (int j = 0; j < GAE1; j++) {
        g_hm  [(size_t)n * 40 + j]      = am[j];
        g_hm  [(size_t)n * 40 + 20 + j] = as_[j];
        g_aggm[(size_t)n * 40 + j]      = d2 * am[j]  + bm[j];
        g_aggm[(size_t)n * 40 + 20 + j] = d2 * as_[j] + bs[j];
    }
}

__global__ void k_edge_m(const int* __restrict__ ei, const float* __restrict__ w) {
    int e = blockIdx.x * blockDim.x + threadIdx.x;
    if (e >= Ee) return;
    int s = ei[e], d = ei[Ee + e];
    float coef = g_dinv[s] * g_dinv[d] * w[e];
    const float4* hp = (const float4*)(g_hm + (size_t)s * 40);
    float4* op = (float4*)(g_aggm + (size_t)d * 40);
#pragma unroll
    for (int q = 0; q < 10; q++) {
        float4 v = hp[q];
        atomicAdd(op + q, make_float4(coef*v.x, coef*v.y, coef*v.z, coef*v.w));
    }
}

__global__ void k_node(const float* __restrict__ eps,
                       const float* __restrict__ Wc, const float* __restrict__ bc,
                       const float* __restrict__ Wg, const float* __restrict__ bg,
                       float* __restrict__ out) {
    int n = blockIdx.x * blockDim.x + threadIdx.x;
    float kl = 0.f;
    if (n < Nn) {
        float fr[FCAT];
#pragma unroll
        for (int j = 0; j < DAE1; j++) fr[j] = g_feat[(size_t)n * FCAT + j];
#pragma unroll
        for (int j = 0; j < GAE1; j++) {
            float mu = g_aggm[(size_t)n * 40 + j];
            float ls = fminf(g_aggm[(size_t)n * 40 + 20 + j], 10.0f);
            float z  = mu + eps[(size_t)n * GAE1 + j] * expf(ls);
            kl += 1.f + 2.f * ls - mu * mu - expf(2.f * ls);
            fr[20 + j] = z;
            g_feat[(size_t)n * FCAT + 20 + j] = z;
            g_fdup[(size_t)n * FCAT + 20 + j] = pack2(z, z);
        }
        float c[CTn];
#pragma unroll
        for (int t = 0; t < CTn; t++) c[t] = bc[t];
#pragma unroll
        for (int k = 0; k < FCAT; k++) {
            float f = fr[k];
#pragma unroll
            for (int t = 0; t < CTn; t++) c[t] += f * Wc[k * CTn + t];
        }
        float sum = 0.f;
#pragma unroll
        for (int t = 0; t < CTn; t++) { c[t] = fmaxf(c[t], 0.f); sum += c[t]; }
        float inv = 1.f / (sum + 1e-6f);
#pragma unroll
        for (int t = 0; t < CTn; t++) out[(size_t)n * CTn + t] = c[t] * inv;
        float g[FEATn];
#pragma unroll
        for (int j = 0; j < FEATn; j++) g[j] = bg[j];
#pragma unroll
        for (int k = 0; k < FCAT; k++) {
            float f = fr[k];
            const float4* wp = (const float4*)(Wg + k * FEATn);
#pragma unroll
            for (int q = 0; q < 16; q++) {
                float4 w = wp[q];
                g[4*q]   += f*w.x; g[4*q+1] += f*w.y; g[4*q+2] += f*w.z; g[4*q+3] += f*w.w;
            }
        }
#pragma unroll
        for (int j = 0; j < FEATn; j++) g_zg[(size_t)n * FEATn + j] = fmaxf(g[j], 0.f);
    }
#pragma unroll
    for (int off = 16; off > 0; off >>= 1) kl += __shfl_down_sync(0xffffffffu, kl, off);
    if ((threadIdx.x & 31) == 0) atomicAdd(&g_acc[2], kl);
}

__global__ void k_loss(const int* __restrict__ ei, const int* __restrict__ nei,
                       const float* __restrict__ w) {
    int e = blockIdx.x * blockDim.x + threadIdx.x;
    int set = blockIdx.y;
    float v = 0.f;
    if (e < Ee) {
        const int* idx = set ? nei : ei;
        int s = idx[e], d = idx[Ee + e];
        const float4* a = (const float4*)(g_zg + (size_t)s * FEATn);
        const float4* b = (const float4*)(g_zg + (size_t)d * FEATn);
        float dot = 0.f;
#pragma unroll
        for (int q = 0; q < 16; q++) {
            float4 av = a[q], bv = b[q];
            dot += av.x*bv.x + av.y*bv.y + av.z*bv.z + av.w*bv.w;
        }
        float p = 1.f / (1.f + expf(-dot));
        float t = set ? p : (p - w[e]);
        v = t * t;
    }
#pragma unroll
    for (int off = 16; off > 0; off >>= 1) v += __shfl_down_sync(0xffffffffu, v, off);
    if ((threadIdx.x & 31) == 0) atomicAdd(&g_acc[set], v);
}

__global__ void k_final(float* __restrict__ out) {
    out[20100000] = g_acc[0] / (float)Ee + g_acc[1] / (float)Ee
                  - 0.5f * g_acc[2] / ((float)Nn * (float)Nn);
}

__global__ __launch_bounds__(256) void k_xdec(const float* __restrict__ Wdec,
                                              const float* __restrict__ bdec,
                                              float* __restrict__ out) {
    __shared__ ull sf[16 * FCAT];
    const int tid = threadIdx.x;
    const int s0 = blockIdx.y * 16;
    for (int idx = tid; idx < 16 * FCAT; idx += 256) {
        int n = min(s0 + idx / FCAT, Nn - 1);
        sf[idx] = g_fdup[(size_t)n * FCAT + idx % FCAT];
    }
    __syncthreads();
    int cp = blockIdx.x * 256 + tid;
    if (cp >= Pp / 2) return;
    const ull* wp = (const ull*)Wdec;
    ull bias = ((const ull*)bdec)[cp];
    ull acc[16];
#pragma unroll
    for (int s = 0; s < 16; s++) acc[s] = bias;
#pragma unroll 4
    for (int k = 0; k < FCAT; k++) {
        ull wv = wp[k * (Pp / 2) + cp];
#pragma unroll
        for (int s = 0; s < 16; s++) fma2(acc[s], sf[s * FCAT + k], wv);
    }
#pragma unroll
    for (int s = 0; s < 16; s++) {
        int n = s0 + s;
        if (n < Nn) *(ull*)(out + 100000 + (size_t)n * Pp + 2 * cp) = acc[s];
    }
}

// pw head: transposed weights + smem-staged stores with per-sg named barriers
__global__ __launch_bounds__(256, 2) void k_pw(const float* __restrict__ bv,
                                               float* __restrict__ out) {
    __shared__ ull   sf[32 * FCAT];
    __shared__ float sbuf[4][640];
    const int tid = threadIdx.x;
    const int s0 = blockIdx.y * 32;
    for (int idx = tid; idx < 32 * FCAT; idx += 256) {
        int n = min(s0 + idx / FCAT, Nn - 1);
        sf[idx] = g_fdup[(size_t)n * FCAT + idx % FCAT];
    }
    __syncthreads();
    const int plocal = tid & 63;
    const int p0 = blockIdx.x * 64;
    const int p  = p0 + plocal;
    const int pc = min(p, Pp - 1);
    const int sg = tid >> 6;
    const int pcount = min(64, Pp - p0);
    const ull* bvp = (const ull*)bv;
    ull acc[8][5];
    {
        ull b0 = bvp[5*pc], b1 = bvp[5*pc+1], b2 = bvp[5*pc+2], b3 = bvp[5*pc+3], b4 = bvp[5*pc+4];
#pragma unroll
        for (int s = 0; s < 8; s++) {
            acc[s][0] = b0; acc[s][1] = b1; acc[s][2] = b2; acc[s][3] = b3; acc[s][4] = b4;
        }
    }
#pragma unroll 4
    for (int k = 0; k < FCAT; k++) {
        ull wv[5];
#pragma unroll
        for (int q = 0; q < 5; q++) wv[q] = g_wvt[(size_t)(k * 5 + q) * Pp + pc];
#pragma unroll
        for (int s = 0; s < 8; s++) {
            ull f = sf[(sg * 8 + s) * FCAT + k];
#pragma unroll
            for (int q = 0; q < 5; q++) fma2(acc[s][q], f, wv[q]);
        }
    }
    // relu + rownorm; per-sg (64-thread) named barriers instead of block syncs
#pragma unroll
    for (int s = 0; s < 8; s++) {
        {
            float v[CTn];
            float sum = 0.f;
#pragma unroll
            for (int q = 0; q < 5; q++) {
                float2 u = unpack2(acc[s][q]);
                v[2*q]   = fmaxf(u.x, 0.f);
                v[2*q+1] = fmaxf(u.y, 0.f);
                sum += v[2*q] + v[2*q+1];
            }
            float inv = 1.f / (sum + 1e-6f);
#pragma unroll
            for (int c = 0; c < CTn; c++) sbuf[sg][plocal * CTn + c] = v[c] * inv;
        }
        asm volatile("bar.sync %0, 64;" :: "r"(sg + 1) : "memory");
        int n = s0 + sg * 8 + s;
        if (n < Nn) {
            float* o = out + 20100001LL + (size_t)n * (Pp * CTn) + (size_t)p0 * CTn;
            int cnt = pcount * CTn;
#pragma unroll
            for (int j = plocal; j < cnt; j += 64) o[j] = sbuf[sg][j];
        }
        asm volatile("bar.sync %0, 64;" :: "r"(sg + 1) : "memory");
    }
}

extern "C" void kernel_launch(void* const* d_in, const int* in_sizes, int n_in,
                              void* d_out, int out_size) {
    const float* x    = (const float*)d_in[0];
    const float* ew   = (const float*)d_in[1];
    const float* eps  = (const float*)d_in[2];
    const float* W1   = (const float*)d_in[3];
    const float* b1   = (const float*)d_in[4];
    const float* W2   = (const float*)d_in[5];
    const float* b2   = (const float*)d_in[6];
    const float* Wf   = (const float*)d_in[7];
    const float* bf   = (const float*)d_in[8];
    const float* Wm   = (const float*)d_in[9];
    const float* bm   = (const float*)d_in[10];
    const float* Ws   = (const float*)d_in[11];
    const float* bs   = (const float*)d_in[12];
    const float* Wdec = (const float*)d_in[13];
    const float* bdec = (const float*)d_in[14];
    const float* Wg   = (const float*)d_in[15];
    const float* bg   = (const float*)d_in[16];
    const float* Wc   = (const float*)d_in[17];
    const float* bc   = (const float*)d_in[18];
    const float* Wv   = (const float*)d_in[19];
    const float* bv   = (const float*)d_in[20];
    const int*   ei   = (const int*)d_in[21];
    const int*   nei  = (const int*)d_in[22];
    float* out = (float*)d_out;

    k_init <<<(Nn + 255) / 256, 256>>>();
    k_deg  <<<Ee / 256, 256>>>(ei, ew);
    k_dinv <<<(Nn + 255) / 256, 256>>>();
    k_gemm1<<<dim3((Nn + 63) / 64, 4), 160>>>(x, W1);          // profile slot 3
    k_wvt  <<<(FCAT * Pp * 5 + 255) / 256, 256>>>(Wv);
    k_dae2 <<<(Nn + 127) / 128, 128>>>(b1, W2, b2);
    k_gcnf_lin<<<(Nn + 127) / 128, 128>>>(Wf, bf);
    k_edge_f  <<<Ee / 128, 128>>>(ei, ew);
    k_gcnm_lin<<<(Nn + 127) / 128, 128>>>(Wm, bm, Ws, bs);
    k_edge_m  <<<Ee / 128, 128>>>(ei, ew);
    k_node <<<(Nn + 127) / 128, 128>>>(eps, Wc, bc, Wg, bg, out);
    k_loss <<<dim3(Ee / 256, 2), 256>>>(ei, nei, ew);
    k_final<<<1, 1>>>(out);
    k_xdec <<<dim3(4, (Nn + 15) / 16), 256>>>(Wdec, bdec, out);
    k_pw   <<<dim3((Pp + 63) / 64, (Nn + 31) / 32), 256>>>(bv, out);
}